// round 8
// baseline (speedup 1.0000x reference)
#include <cuda_runtime.h>
#include <cstdint>
#include <math.h>

#define T_LEN  2048
#define D_EMB  300
#define H_DIM  256
#define G4     1024
#define K_TAGS 48
#define START_TAG 46
#define STOP_TAG  47

// ---------------- scratch (device globals; no allocation) ----------------
__device__ float g_x[T_LEN * D_EMB];        // gathered embeddings [T, D]
__device__ float g_xg[2][T_LEN * G4];       // input projections per dir [T, 4H]
__device__ float g_hs[2][T_LEN * H_DIM];    // hidden states per dir, time-aligned
__device__ float g_feats[T_LEN * K_TAGS];   // emission features [T, K]

// ---------------- f32x2 helpers ----------------
__device__ __forceinline__ unsigned long long pack2(float lo, float hi) {
    unsigned long long r;
    asm("mov.b64 %0, {%1,%2};" : "=l"(r) : "f"(lo), "f"(hi));
    return r;
}
__device__ __forceinline__ void unpack2(unsigned long long v, float& lo, float& hi) {
    asm("mov.b64 {%0,%1}, %2;" : "=f"(lo), "=f"(hi) : "l"(v));
}
__device__ __forceinline__ unsigned long long mul2(unsigned long long a, unsigned long long b) {
    unsigned long long d;
    asm("mul.rn.f32x2 %0, %1, %2;" : "=l"(d) : "l"(a), "l"(b));
    return d;
}
__device__ __forceinline__ unsigned long long fma2(unsigned long long a, unsigned long long b,
                                                   unsigned long long c) {
    unsigned long long d;
    asm("fma.rn.f32x2 %0, %1, %2, %3;" : "=l"(d) : "l"(a), "l"(b), "l"(c));
    return d;
}

// ---------------- 1) embedding gather ----------------
__global__ void gather_kernel(const int* __restrict__ sent,
                              const float* __restrict__ E) {
    int idx = blockIdx.x * blockDim.x + threadIdx.x;
    int total = T_LEN * D_EMB;
    for (; idx < total; idx += gridDim.x * blockDim.x) {
        int t = idx / D_EMB;
        int d = idx - t * D_EMB;
        long long row = sent[t];
        g_x[idx] = E[row * D_EMB + d];
    }
}

// ---------------- 2) xg GEMM: [T,D] @ [4H,D]^T + (b_ih + b_hh) ----------------
#define BM 64
#define BN 64
#define BK 12
__global__ void xg_gemm_kernel(const float* __restrict__ Wf,
                               const float* __restrict__ Wb,
                               const float* __restrict__ bihf,
                               const float* __restrict__ bhhf,
                               const float* __restrict__ bihb,
                               const float* __restrict__ bhhb) {
    int dir = blockIdx.z;
    const float* W  = dir ? Wb   : Wf;
    const float* b1 = dir ? bihb : bihf;
    const float* b2 = dir ? bhhb : bhhf;

    __shared__ float As[BK][BM];
    __shared__ float Bs[BK][BN];

    int t0 = blockIdx.x * BM;
    int r0 = blockIdx.y * BN;
    int tid = threadIdx.x;           // 256 threads
    int tx = tid & 15;
    int ty = tid >> 4;

    float acc[4][4];
#pragma unroll
    for (int i = 0; i < 4; i++)
#pragma unroll
        for (int j = 0; j < 4; j++) acc[i][j] = 0.f;

    for (int k0 = 0; k0 < D_EMB; k0 += BK) {   // 300 = 25 * 12, no guards
#pragma unroll
        for (int l2 = 0; l2 < 3; l2++) {
            int idx = tid + l2 * 256;       // 0..767
            int row = idx / 12;             // 0..63
            int kk  = idx - row * 12;
            int tg = t0 + row;
            int ts = dir ? (T_LEN - 1 - tg) : tg;
            As[kk][row] = g_x[ts * D_EMB + k0 + kk];
            Bs[kk][row] = W[(r0 + row) * D_EMB + k0 + kk];
        }
        __syncthreads();
#pragma unroll
        for (int kk = 0; kk < BK; kk++) {
            float ra[4], rb[4];
#pragma unroll
            for (int i = 0; i < 4; i++) ra[i] = As[kk][ty * 4 + i];
#pragma unroll
            for (int j = 0; j < 4; j++) rb[j] = Bs[kk][tx * 4 + j];
#pragma unroll
            for (int i = 0; i < 4; i++)
#pragma unroll
                for (int j = 0; j < 4; j++) acc[i][j] += ra[i] * rb[j];
        }
        __syncthreads();
    }

#pragma unroll
    for (int i = 0; i < 4; i++) {
        int t = t0 + ty * 4 + i;
#pragma unroll
        for (int j = 0; j < 4; j++) {
            int r = r0 + tx * 4 + j;
            g_xg[dir][t * G4 + r] = acc[i][j] + b1[r] + b2[r];
        }
    }
}

// ---------------- 3) LSTM recurrence: 8-CTA cluster, tagged-slot exchange ----------------
// CTA rank owns hidden units [rank*32, rank*32+32). Warp w owns units 2w,2w+1.
// NO barrier / mbarrier in the step loop. h exchange is self-announcing:
// each warp's h pair is stored as a 16B slot (h0, h0^seq, h1, h1^seq) into all
// 8 CTAs (lanes 0-7, one st.shared::cluster.v4 warp instruction), seq = t+1,
// double-buffered by parity. Consumers spin-load exactly the 4 slots covering
// their own k-chunk and validate the XOR checksums (each 4B data word is
// validated against its own tag word, so store-splitting granularity is
// irrelevant and no fence is needed). A producer can only write seq t+2 into a
// buffer after consuming all seq-t+1 slots, which requires every warp to have
// finished READING the seq-t buffer -> double buffering is sufficient.
// Initial zeroed buffers pass the check for seq=0 with h=0 == correct init.
// Reduce-scatter keeps rows at lane bits <4,3,2> (no realign shuffle):
// 3 scatter rounds + xor1 + xor2 = 5 dependent shfl rounds.
__global__ void __launch_bounds__(512, 1) __cluster_dims__(8, 1, 1)
lstm_kernel8(const float* __restrict__ Whf, const float* __restrict__ Whb) {
    __shared__ __align__(16) float4 slots[2][128];   // [parity][unit-pair]

    int dir = blockIdx.y;
    const float* Whh = dir ? Whb : Whf;
    const float* xg = g_xg[dir];
    float* hs = g_hs[dir];

    uint32_t rank;
    asm("mov.u32 %0, %%cluster_ctarank;" : "=r"(rank));

    int tid = threadIdx.x;
    int w = tid >> 5;
    int l = tid & 31;
    int r = (l >> 2) & 7;          // W row this lane finalizes (lane bits 4,3,2)
    int gate = r & 3;
    int du = r >> 2;               // which of the warp's 2 units this lane owns
    int xg_col = gate * H_DIM + (int)rank * 32 + 2 * w + du;

    // weight rows q = du*4+gate (bit2=du, bits1:0=gate); lane covers k [8l,8l+8)
    unsigned long long w2[8][4];
#pragma unroll
    for (int q = 0; q < 8; q++) {
        int row = (q & 3) * H_DIM + (int)rank * 32 + 2 * w + (q >> 2);
        const float4* p = (const float4*)(Whh + (size_t)row * H_DIM + l * 8);
        float4 a = p[0];
        float4 b = p[1];
        w2[q][0] = pack2(a.x, a.y); w2[q][1] = pack2(a.z, a.w);
        w2[q][2] = pack2(b.x, b.y); w2[q][3] = pack2(b.z, b.w);
    }

    // zero both slot buffers (valid seq=0 state: data 0, tag 0 = 0^0)
    for (int i = tid; i < 2 * 128 * 4; i += 512) ((float*)slots)[i] = 0.f;

    uint32_t sb = (uint32_t)__cvta_generic_to_shared(&slots[0][0]);
    uint32_t rS[8];
#pragma unroll
    for (int tg = 0; tg < 8; tg++) {
        asm("mapa.shared::cluster.u32 %0, %1, %2;" : "=r"(rS[tg]) : "r"(sb), "r"(tg));
    }

    __syncthreads();
    // all CTAs' buffers zeroed before any remote traffic
    asm volatile("barrier.cluster.arrive.aligned;" ::: "memory");
    asm volatile("barrier.cluster.wait.aligned;" ::: "memory");

    float c_reg = 0.f;
    float xg_pref = xg[xg_col];
    const float LOG2E = 1.4426950408889634f;
    int my_slot = (int)rank * 16 + w;      // this warp's unit-pair slot index

#pragma unroll 1
    for (int t = 0; t < T_LEN; t++) {
        uint32_t par = (uint32_t)(t & 1);
        uint32_t want = (uint32_t)t;

        // spin-load the 4 slots covering this lane's k-chunk (units 8l..8l+7)
        uint32_t base = sb + par * 2048u + (uint32_t)l * 64u;
        float4 s0, s1, s2, s3;
        bool ok;
        do {
            asm volatile("ld.volatile.shared.v4.f32 {%0,%1,%2,%3}, [%4];"
                         : "=f"(s0.x), "=f"(s0.y), "=f"(s0.z), "=f"(s0.w)
                         : "r"(base));
            asm volatile("ld.volatile.shared.v4.f32 {%0,%1,%2,%3}, [%4];"
                         : "=f"(s1.x), "=f"(s1.y), "=f"(s1.z), "=f"(s1.w)
                         : "r"(base + 16));
            asm volatile("ld.volatile.shared.v4.f32 {%0,%1,%2,%3}, [%4];"
                         : "=f"(s2.x), "=f"(s2.y), "=f"(s2.z), "=f"(s2.w)
                         : "r"(base + 32));
            asm volatile("ld.volatile.shared.v4.f32 {%0,%1,%2,%3}, [%4];"
                         : "=f"(s3.x), "=f"(s3.y), "=f"(s3.z), "=f"(s3.w)
                         : "r"(base + 48));
            ok = (__float_as_uint(s0.y) == (__float_as_uint(s0.x) ^ want)) &&
                 (__float_as_uint(s0.w) == (__float_as_uint(s0.z) ^ want)) &&
                 (__float_as_uint(s1.y) == (__float_as_uint(s1.x) ^ want)) &&
                 (__float_as_uint(s1.w) == (__float_as_uint(s1.z) ^ want)) &&
                 (__float_as_uint(s2.y) == (__float_as_uint(s2.x) ^ want)) &&
                 (__float_as_uint(s2.w) == (__float_as_uint(s2.z) ^ want)) &&
                 (__float_as_uint(s3.y) == (__float_as_uint(s3.x) ^ want)) &&
                 (__float_as_uint(s3.w) == (__float_as_uint(s3.z) ^ want));
        } while (!__all_sync(0xffffffffu, ok));

        unsigned long long h2[4] = { pack2(s0.x, s0.z), pack2(s1.x, s1.z),
                                     pack2(s2.x, s2.z), pack2(s3.x, s3.z) };
        float v[8];
#pragma unroll
        for (int q = 0; q < 8; q++) {
            unsigned long long acc = mul2(w2[q][0], h2[0]);
            acc = fma2(w2[q][1], h2[1], acc);
            acc = fma2(w2[q][2], h2[2], acc);
            acc = fma2(w2[q][3], h2[3], acc);
            float lo, hi;
            unpack2(acc, lo, hi);
            v[q] = lo + hi;
        }

        // reduce-scatter onto lane bits 4,3,2 (row = (l>>2)&7)
#pragma unroll
        for (int i = 0; i < 4; i++) {
            float send = (l & 16) ? v[i] : v[i + 4];
            float recv = __shfl_xor_sync(0xffffffffu, send, 16);
            float keep = (l & 16) ? v[i + 4] : v[i];
            v[i] = keep + recv;
        }
#pragma unroll
        for (int i = 0; i < 2; i++) {
            float send = (l & 8) ? v[i] : v[i + 2];
            float recv = __shfl_xor_sync(0xffffffffu, send, 8);
            float keep = (l & 8) ? v[i + 2] : v[i];
            v[i] = keep + recv;
        }
        {
            float send = (l & 4) ? v[0] : v[1];
            float recv = __shfl_xor_sync(0xffffffffu, send, 4);
            float keep = (l & 4) ? v[1] : v[0];
            v[0] = keep + recv;
        }
        // combine the 4 partials living at lane bits 1,0
        float x = v[0];
        x += __shfl_xor_sync(0xffffffffu, x, 1);
        x += __shfl_xor_sync(0xffffffffu, x, 2);

        float pre = x + xg_pref;
        if (t + 1 < T_LEN)
            xg_pref = xg[(size_t)(t + 1) * G4 + xg_col];

        // branch-free activation: gate 2 -> tanh, else sigmoid (EX2 + RCP)
        float aa = (gate == 2) ? (2.f * LOG2E) : (-LOG2E);
        float e = exp2f(aa * pre);
        float z = __fdividef(1.f, 1.f + e);
        float act = (gate == 2) ? fmaf(-2.f, z, 1.f) : z;

        // gather i,f,g,o for this lane's unit du: rows du*4+g at lanes 16du+4g
        int gbase = du << 4;
        float iv = __shfl_sync(0xffffffffu, act, gbase);
        float fv = __shfl_sync(0xffffffffu, act, gbase + 4);
        float gg = __shfl_sync(0xffffffffu, act, gbase + 8);
        float ov = __shfl_sync(0xffffffffu, act, gbase + 12);

        c_reg = fmaf(fv, c_reg, iv * gg);
        float e2 = exp2f(2.f * LOG2E * c_reg);
        float hval = ov * fmaf(-2.f, __fdividef(1.f, 1.f + e2), 1.f);

        // h pair: unit 2w computed on lanes 0-15 (du=0), 2w+1 on lanes 16-31
        float h0 = __shfl_sync(0xffffffffu, hval, 0);
        float h1 = __shfl_sync(0xffffffffu, hval, 16);

        uint32_t seq = (uint32_t)(t + 1);
        float tg0 = __uint_as_float(__float_as_uint(h0) ^ seq);
        float tg1 = __uint_as_float(__float_as_uint(h1) ^ seq);
        uint32_t off = (1u - par) * 2048u + (uint32_t)my_slot * 16u;
        if (l < 8) {
            asm volatile("st.shared::cluster.v4.f32 [%0], {%1,%2,%3,%4};"
                         :: "r"(rS[l] + off), "f"(h0), "f"(tg0), "f"(h1), "f"(tg1)
                         : "memory");
        }
        if (l == 8) {
            int tout = dir ? (T_LEN - 1 - t) : t;
            *(float2*)&hs[(size_t)tout * H_DIM + rank * 32 + 2 * w] =
                make_float2(h0, h1);
        }
    }

    // no CTA may exit while remote stores may still target its smem
    asm volatile("barrier.cluster.arrive.aligned;" ::: "memory");
    asm volatile("barrier.cluster.wait.aligned;" ::: "memory");
}

// ---------------- 4) feats GEMM: [T,512] @ [48,512]^T + b_out ----------------
#define FT_TT 64
__global__ void feats_gemm_kernel(const float* __restrict__ W_out,
                                  const float* __restrict__ b_out) {
    __shared__ float As[32][FT_TT];   // [j][t]
    __shared__ float Bs[32][K_TAGS];  // [j][k]

    int t0 = blockIdx.x * FT_TT;
    int tid = threadIdx.x;            // 256
    int tx = tid & 15;                // k-group: 3 tags
    int ty = tid >> 4;                // t-group: 4 steps

    float acc[4][3];
#pragma unroll
    for (int i = 0; i < 4; i++)
#pragma unroll
        for (int k = 0; k < 3; k++) acc[i][k] = 0.f;

    for (int j0 = 0; j0 < 2 * H_DIM; j0 += 32) {
#pragma unroll
        for (int i = 0; i < 8; i++) {
            int idx = tid + i * 256;        // 0..2047
            int jj = idx & 31;
            int tt = idx >> 5;
            int j = j0 + jj;
            float hv = (j < H_DIM)
                ? g_hs[0][(size_t)(t0 + tt) * H_DIM + j]
                : g_hs[1][(size_t)(t0 + tt) * H_DIM + (j - H_DIM)];
            As[jj][tt] = hv;
        }
#pragma unroll
        for (int i = 0; i < 6; i++) {
            int idx = tid + i * 256;        // 0..1535
            int k = idx % K_TAGS;
            int jj = idx / K_TAGS;
            Bs[jj][k] = W_out[(size_t)k * (2 * H_DIM) + j0 + jj];
        }
        __syncthreads();
#pragma unroll
        for (int jj = 0; jj < 32; jj++) {
            float a[4], b[3];
#pragma unroll
            for (int i = 0; i < 4; i++) a[i] = As[jj][ty * 4 + i];
#pragma unroll
            for (int k = 0; k < 3; k++) b[k] = Bs[jj][tx * 3 + k];
#pragma unroll
            for (int i = 0; i < 4; i++)
#pragma unroll
                for (int k = 0; k < 3; k++) acc[i][k] += a[i] * b[k];
        }
        __syncthreads();
    }

#pragma unroll
    for (int i = 0; i < 4; i++) {
        int t = t0 + ty * 4 + i;
#pragma unroll
        for (int k = 0; k < 3; k++) {
            int kk = tx * 3 + k;
            g_feats[t * K_TAGS + kk] = acc[i][k] + b_out[kk];
        }
    }
}

// ---------------- 5) Viterbi + backtrace (single CTA, 96 threads) ----------------
#define VIT_SMEM (T_LEN * K_TAGS + 2 * K_TAGS * 4 + K_TAGS * 4 + K_TAGS * 4 + 16)
extern __shared__ unsigned char vit_smem[];
__global__ void viterbi_kernel(const float* __restrict__ trans,
                               float* __restrict__ out) {
    unsigned char* bptr = vit_smem;                          // [T][48] u8 = 96KB
    float* fv = (float*)(vit_smem + T_LEN * K_TAGS);         // [2][48]
    float* ps = fv + 2 * K_TAGS;                             // [48] hi-partial score
    int*   pa = (int*)(ps + K_TAGS);                         // [48] hi-partial arg
    int tid = threadIdx.x;  // 96
    int tag = (tid < K_TAGS) ? tid : (tid - K_TAGS);
    int jlo = (tid < K_TAGS) ? 0 : 24;                       // prev range start

    float tr[24];
#pragma unroll
    for (int j = 0; j < 24; j++) tr[j] = trans[tag * K_TAGS + jlo + j];
    if (tid < K_TAGS) fv[tid] = (tid == START_TAG) ? 0.f : -10000.f;
    float featp = g_feats[tag];
    __syncthreads();

    for (int t = 0; t < T_LEN; t++) {
        int cur = (t & 1) * K_TAGS;
        int nxt = K_TAGS - cur;

        float b0 = -3.4e38f, b1 = -3.4e38f, b2 = -3.4e38f, b3 = -3.4e38f;
        int a0 = 0, a1 = 1, a2 = 2, a3 = 3;
#pragma unroll
        for (int j = 0; j < 24; j += 4) {
            float s0 = fv[cur + jlo + j]     + tr[j];
            float s1 = fv[cur + jlo + j + 1] + tr[j + 1];
            float s2 = fv[cur + jlo + j + 2] + tr[j + 2];
            float s3 = fv[cur + jlo + j + 3] + tr[j + 3];
            if (s0 > b0) { b0 = s0; a0 = j; }
            if (s1 > b1) { b1 = s1; a1 = j + 1; }
            if (s2 > b2) { b2 = s2; a2 = j + 2; }
            if (s3 > b3) { b3 = s3; a3 = j + 3; }
        }
        float bv = b0; int ba = a0;
        if (b1 > bv || (b1 == bv && a1 < ba)) { bv = b1; ba = a1; }
        if (b2 > bv || (b2 == bv && a2 < ba)) { bv = b2; ba = a2; }
        if (b3 > bv || (b3 == bv && a3 < ba)) { bv = b3; ba = a3; }
        ba += jlo;

        if (tid >= K_TAGS) {           // upper half publishes its partial
            ps[tag] = bv;
            pa[tag] = ba;
        }
        __syncthreads();

        if (tid < K_TAGS) {
            float hv = ps[tag];
            // strict > : ties go to the low half (smaller indices) = jnp.argmax
            if (hv > bv) { bv = hv; ba = pa[tag]; }
            float feat = featp;
            if (t + 1 < T_LEN) featp = g_feats[(t + 1) * K_TAGS + tag];
            fv[nxt + tag] = bv + feat;
            bptr[t * K_TAGS + tag] = (unsigned char)ba;
        } else {
            if (t + 1 < T_LEN) featp = g_feats[(t + 1) * K_TAGS + tag];
        }
        __syncthreads();
    }

    if (tid == 0) {
        int cur = (T_LEN & 1) * K_TAGS;   // = 0 for even T
        float best = -3.4e38f;
        int btag = 0;
#pragma unroll
        for (int j = 0; j < K_TAGS; j++) {
            float s = fv[cur + j] + trans[STOP_TAG * K_TAGS + j];
            if (s > best) { best = s; btag = j; }
        }
        out[0] = best;
        for (int t = T_LEN - 1; t >= 0; t--) {
            out[1 + t] = (float)btag;
            btag = bptr[t * K_TAGS + btag];
        }
    }
}

// ---------------- launch ----------------
extern "C" void kernel_launch(void* const* d_in, const int* in_sizes, int n_in,
                              void* d_out, int out_size) {
    const int*   sent   = (const int*)d_in[0];
    const float* E      = (const float*)d_in[1];
    const float* W_ih_f = (const float*)d_in[2];
    const float* W_hh_f = (const float*)d_in[3];
    const float* b_ih_f = (const float*)d_in[4];
    const float* b_hh_f = (const float*)d_in[5];
    const float* W_ih_b = (const float*)d_in[6];
    const float* W_hh_b = (const float*)d_in[7];
    const float* b_ih_b = (const float*)d_in[8];
    const float* b_hh_b = (const float*)d_in[9];
    const float* W_out  = (const float*)d_in[10];
    const float* b_out  = (const float*)d_in[11];
    const float* trans  = (const float*)d_in[12];
    float* out = (float*)d_out;

    cudaFuncSetAttribute(viterbi_kernel,
                         cudaFuncAttributeMaxDynamicSharedMemorySize, VIT_SMEM);

    gather_kernel<<<256, 256>>>(sent, E);

    dim3 ggrid(T_LEN / BM, G4 / BN, 2);
    xg_gemm_kernel<<<ggrid, 256>>>(W_ih_f, W_ih_b, b_ih_f, b_hh_f, b_ih_b, b_hh_b);

    lstm_kernel8<<<dim3(8, 2, 1), 512>>>(W_hh_f, W_hh_b);

    feats_gemm_kernel<<<T_LEN / FT_TT, 256>>>(W_out, b_out);

    viterbi_kernel<<<1, 96, VIT_SMEM>>>(trans, out);
}

// round 9
// speedup vs baseline: 1.5222x; 1.5222x over previous
#include <cuda_runtime.h>
#include <cstdint>
#include <math.h>

#define T_LEN  2048
#define D_EMB  300
#define H_DIM  256
#define G4     1024
#define K_TAGS 48
#define START_TAG 46
#define STOP_TAG  47

// ---------------- scratch (device globals; no allocation) ----------------
__device__ float g_x[T_LEN * D_EMB];        // gathered embeddings [T, D]
__device__ float g_xg[2][T_LEN * G4];       // input projections per dir [T, 4H]
__device__ float g_hs[2][T_LEN * H_DIM];    // hidden states per dir, time-aligned
__device__ float g_feats[T_LEN * K_TAGS];   // emission features [T, K]

// ---------------- f32x2 helpers ----------------
__device__ __forceinline__ unsigned long long pack2(float lo, float hi) {
    unsigned long long r;
    asm("mov.b64 %0, {%1,%2};" : "=l"(r) : "f"(lo), "f"(hi));
    return r;
}
__device__ __forceinline__ void unpack2(unsigned long long v, float& lo, float& hi) {
    asm("mov.b64 {%0,%1}, %2;" : "=f"(lo), "=f"(hi) : "l"(v));
}
__device__ __forceinline__ unsigned long long mul2(unsigned long long a, unsigned long long b) {
    unsigned long long d;
    asm("mul.rn.f32x2 %0, %1, %2;" : "=l"(d) : "l"(a), "l"(b));
    return d;
}
__device__ __forceinline__ unsigned long long fma2(unsigned long long a, unsigned long long b,
                                                   unsigned long long c) {
    unsigned long long d;
    asm("fma.rn.f32x2 %0, %1, %2, %3;" : "=l"(d) : "l"(a), "l"(b), "l"(c));
    return d;
}

// ---------------- 1) embedding gather ----------------
__global__ void gather_kernel(const int* __restrict__ sent,
                              const float* __restrict__ E) {
    int idx = blockIdx.x * blockDim.x + threadIdx.x;
    int total = T_LEN * D_EMB;
    for (; idx < total; idx += gridDim.x * blockDim.x) {
        int t = idx / D_EMB;
        int d = idx - t * D_EMB;
        long long row = sent[t];
        g_x[idx] = E[row * D_EMB + d];
    }
}

// ---------------- 2) xg GEMM: [T,D] @ [4H,D]^T + (b_ih + b_hh) ----------------
#define BM 64
#define BN 64
#define BK 12
__global__ void xg_gemm_kernel(const float* __restrict__ Wf,
                               const float* __restrict__ Wb,
                               const float* __restrict__ bihf,
                               const float* __restrict__ bhhf,
                               const float* __restrict__ bihb,
                               const float* __restrict__ bhhb) {
    int dir = blockIdx.z;
    const float* W  = dir ? Wb   : Wf;
    const float* b1 = dir ? bihb : bihf;
    const float* b2 = dir ? bhhb : bhhf;

    __shared__ float As[BK][BM];
    __shared__ float Bs[BK][BN];

    int t0 = blockIdx.x * BM;
    int r0 = blockIdx.y * BN;
    int tid = threadIdx.x;           // 256 threads
    int tx = tid & 15;
    int ty = tid >> 4;

    float acc[4][4];
#pragma unroll
    for (int i = 0; i < 4; i++)
#pragma unroll
        for (int j = 0; j < 4; j++) acc[i][j] = 0.f;

    for (int k0 = 0; k0 < D_EMB; k0 += BK) {   // 300 = 25 * 12, no guards
#pragma unroll
        for (int l2 = 0; l2 < 3; l2++) {
            int idx = tid + l2 * 256;       // 0..767
            int row = idx / 12;             // 0..63
            int kk  = idx - row * 12;
            int tg = t0 + row;
            int ts = dir ? (T_LEN - 1 - tg) : tg;
            As[kk][row] = g_x[ts * D_EMB + k0 + kk];
            Bs[kk][row] = W[(r0 + row) * D_EMB + k0 + kk];
        }
        __syncthreads();
#pragma unroll
        for (int kk = 0; kk < BK; kk++) {
            float ra[4], rb[4];
#pragma unroll
            for (int i = 0; i < 4; i++) ra[i] = As[kk][ty * 4 + i];
#pragma unroll
            for (int j = 0; j < 4; j++) rb[j] = Bs[kk][tx * 4 + j];
#pragma unroll
            for (int i = 0; i < 4; i++)
#pragma unroll
                for (int j = 0; j < 4; j++) acc[i][j] += ra[i] * rb[j];
        }
        __syncthreads();
    }

#pragma unroll
    for (int i = 0; i < 4; i++) {
        int t = t0 + ty * 4 + i;
#pragma unroll
        for (int j = 0; j < 4; j++) {
            int r = r0 + tx * 4 + j;
            g_xg[dir][t * G4 + r] = acc[i][j] + b1[r] + b2[r];
        }
    }
}

// ---------------- 3) LSTM recurrence: 8-CTA cluster per direction ----------------
// R6's proven sync protocol (split barrier.cluster per step) + R8's proven
// shorter compute layout: rows land on lane bits <4,3,2> after 3 scatter
// rounds, partials combine over bits <1,0> (2 rounds) -> 5 dependent shfl
// rounds total, no realign. Gate gather: rows du*4+g live at lanes 16du+4g.
// h pair exchange: single shfl_xor(16). Lanes 0-7 fan the packed h pair to
// all 8 CTAs in one warp store instruction, then split barrier.
__global__ void __launch_bounds__(512, 1) __cluster_dims__(8, 1, 1)
lstm_kernel8(const float* __restrict__ Whf, const float* __restrict__ Whb) {
    __shared__ float h_buf[2][H_DIM];

    int dir = blockIdx.y;
    const float* Whh = dir ? Whb : Whf;
    const float* xg = g_xg[dir];
    float* hs = g_hs[dir];

    uint32_t rank;
    asm("mov.u32 %0, %%cluster_ctarank;" : "=r"(rank));

    int tid = threadIdx.x;
    int w = tid >> 5;
    int l = tid & 31;
    int r = (l >> 2) & 7;          // W row this lane finalizes (lane bits 4,3,2)
    int gate = r & 3;
    int du = r >> 2;               // which of the warp's 2 units (== l>>4)
    int xg_col = gate * H_DIM + (int)rank * 32 + 2 * w + du;

    // weight rows q: gate = q&3, unit-offset = q>>2; lane covers k [8l,8l+8)
    unsigned long long w2[8][4];
#pragma unroll
    for (int q = 0; q < 8; q++) {
        int row = (q & 3) * H_DIM + (int)rank * 32 + 2 * w + (q >> 2);
        const float4* p = (const float4*)(Whh + (size_t)row * H_DIM + l * 8);
        float4 a = p[0];
        float4 b = p[1];
        w2[q][0] = pack2(a.x, a.y); w2[q][1] = pack2(a.z, a.w);
        w2[q][2] = pack2(b.x, b.y); w2[q][3] = pack2(b.z, b.w);
    }

    if (tid < 2 * H_DIM) ((float*)h_buf)[tid] = 0.f;
    uint32_t hb = (uint32_t)__cvta_generic_to_shared(&h_buf[0][0]);

    uint32_t rH[8];
#pragma unroll
    for (int tg = 0; tg < 8; tg++) {
        asm("mapa.shared::cluster.u32 %0, %1, %2;" : "=r"(rH[tg]) : "r"(hb), "r"(tg));
    }

    __syncthreads();
    asm volatile("barrier.cluster.arrive.aligned;" ::: "memory");
    asm volatile("barrier.cluster.wait.aligned;" ::: "memory");

    float c_reg = 0.f;
    float xg_pref = xg[xg_col];
    const float LOG2E = 1.4426950408889634f;
    // per-lane activation constants (hoisted: gate fixed per lane)
    const float act_a = (gate == 2) ? (2.f * LOG2E) : (-LOG2E);
    const bool  is_tanh = (gate == 2);

#pragma unroll 1
    for (int t = 0; t < T_LEN; t++) {
        int cur = t & 1;
        int nxt = cur ^ 1;

        // issue next-step xg load at the top of the step (off critical path)
        float xg_next = 0.f;
        if (t + 1 < T_LEN)
            xg_next = xg[(size_t)(t + 1) * G4 + xg_col];

        float4 ha = *(const float4*)&h_buf[cur][l * 8];
        float4 hc = *(const float4*)&h_buf[cur][l * 8 + 4];
        unsigned long long h2[4] = { pack2(ha.x, ha.y), pack2(ha.z, ha.w),
                                     pack2(hc.x, hc.y), pack2(hc.z, hc.w) };
        float v[8];
#pragma unroll
        for (int q = 0; q < 8; q++) {
            unsigned long long acc = mul2(w2[q][0], h2[0]);
            acc = fma2(w2[q][1], h2[1], acc);
            acc = fma2(w2[q][2], h2[2], acc);
            acc = fma2(w2[q][3], h2[3], acc);
            float lo, hi;
            unpack2(acc, lo, hi);
            v[q] = lo + hi;
        }

        // reduce-scatter onto lane bits 4,3,2 (row = (l>>2)&7)
#pragma unroll
        for (int i = 0; i < 4; i++) {
            float send = (l & 16) ? v[i] : v[i + 4];
            float recv = __shfl_xor_sync(0xffffffffu, send, 16);
            float keep = (l & 16) ? v[i + 4] : v[i];
            v[i] = keep + recv;
        }
#pragma unroll
        for (int i = 0; i < 2; i++) {
            float send = (l & 8) ? v[i] : v[i + 2];
            float recv = __shfl_xor_sync(0xffffffffu, send, 8);
            float keep = (l & 8) ? v[i + 2] : v[i];
            v[i] = keep + recv;
        }
        {
            float send = (l & 4) ? v[0] : v[1];
            float recv = __shfl_xor_sync(0xffffffffu, send, 4);
            float keep = (l & 4) ? v[1] : v[0];
            v[0] = keep + recv;
        }
        // combine the 4 partials living at lane bits 1,0
        float x = v[0];
        x += __shfl_xor_sync(0xffffffffu, x, 1);
        x += __shfl_xor_sync(0xffffffffu, x, 2);

        float pre = x + xg_pref;
        xg_pref = xg_next;

        // branch-free activation: gate 2 -> tanh, else sigmoid (EX2 + RCP)
        float e = exp2f(act_a * pre);
        float z = __fdividef(1.f, 1.f + e);
        float act = is_tanh ? fmaf(-2.f, z, 1.f) : z;

        // gather i,f,g,o for this lane's unit du: rows du*4+g at lanes 16du+4g
        int gbase = du << 4;
        float iv = __shfl_sync(0xffffffffu, act, gbase);
        float fv = __shfl_sync(0xffffffffu, act, gbase + 4);
        float gg = __shfl_sync(0xffffffffu, act, gbase + 8);
        float ov = __shfl_sync(0xffffffffu, act, gbase + 12);

        c_reg = fmaf(fv, c_reg, iv * gg);
        float e2 = exp2f(2.f * LOG2E * c_reg);
        float hval = ov * fmaf(-2.f, __fdividef(1.f, 1.f + e2), 1.f);
        // hval identical within each du half (lanes 0-15: unit 2w; 16-31: 2w+1)

        // single xor-16: every lane obtains the other unit's h
        float h_other = __shfl_xor_sync(0xffffffffu, hval, 16);

        uint32_t off = (uint32_t)((nxt * H_DIM + (int)rank * 32 + 2 * w) * 4);
        if (l < 8) {   // lanes 0-7: du=0 -> hval=h0, h_other=h1
            unsigned long long pk = pack2(hval, h_other);
            asm volatile("st.shared::cluster.b64 [%0], %1;"
                         :: "r"(rH[l] + off), "l"(pk) : "memory");
        }

        asm volatile("barrier.cluster.arrive.aligned;" ::: "memory");

        if (l == 8) {  // du=0: hval=h0, h_other=h1
            int tout = dir ? (T_LEN - 1 - t) : t;
            *(float2*)&hs[(size_t)tout * H_DIM + rank * 32 + 2 * w] =
                make_float2(hval, h_other);
        }

        asm volatile("barrier.cluster.wait.aligned;" ::: "memory");
    }

    asm volatile("barrier.cluster.arrive.aligned;" ::: "memory");
    asm volatile("barrier.cluster.wait.aligned;" ::: "memory");
}

// ---------------- 4) feats GEMM: [T,512] @ [48,512]^T + b_out ----------------
#define FT_TT 64
__global__ void feats_gemm_kernel(const float* __restrict__ W_out,
                                  const float* __restrict__ b_out) {
    __shared__ float As[32][FT_TT];   // [j][t]
    __shared__ float Bs[32][K_TAGS];  // [j][k]

    int t0 = blockIdx.x * FT_TT;
    int tid = threadIdx.x;            // 256
    int tx = tid & 15;                // k-group: 3 tags
    int ty = tid >> 4;                // t-group: 4 steps

    float acc[4][3];
#pragma unroll
    for (int i = 0; i < 4; i++)
#pragma unroll
        for (int k = 0; k < 3; k++) acc[i][k] = 0.f;

    for (int j0 = 0; j0 < 2 * H_DIM; j0 += 32) {
#pragma unroll
        for (int i = 0; i < 8; i++) {
            int idx = tid + i * 256;        // 0..2047
            int jj = idx & 31;
            int tt = idx >> 5;
            int j = j0 + jj;
            float hv = (j < H_DIM)
                ? g_hs[0][(size_t)(t0 + tt) * H_DIM + j]
                : g_hs[1][(size_t)(t0 + tt) * H_DIM + (j - H_DIM)];
            As[jj][tt] = hv;
        }
        // coalesced W_out load: consecutive threads read consecutive j
#pragma unroll
        for (int i = 0; i < 6; i++) {
            int idx = tid + i * 256;        // 0..1535 = 32 j x 48 k
            int jj = idx & 31;
            int k = idx >> 5;               // 0..47
            Bs[jj][k] = W_out[(size_t)k * (2 * H_DIM) + j0 + jj];
        }
        __syncthreads();
#pragma unroll
        for (int jj = 0; jj < 32; jj++) {
            float a[4], b[3];
#pragma unroll
            for (int i = 0; i < 4; i++) a[i] = As[jj][ty * 4 + i];
#pragma unroll
            for (int k = 0; k < 3; k++) b[k] = Bs[jj][tx * 3 + k];
#pragma unroll
            for (int i = 0; i < 4; i++)
#pragma unroll
                for (int k = 0; k < 3; k++) acc[i][k] += a[i] * b[k];
        }
        __syncthreads();
    }

#pragma unroll
    for (int i = 0; i < 4; i++) {
        int t = t0 + ty * 4 + i;
#pragma unroll
        for (int k = 0; k < 3; k++) {
            int kk = tx * 3 + k;
            g_feats[t * K_TAGS + kk] = acc[i][k] + b_out[kk];
        }
    }
}

// ---------------- 5) Viterbi + backtrace (single CTA, 96 threads) ----------------
#define VIT_SMEM (T_LEN * K_TAGS + 2 * K_TAGS * 4 + K_TAGS * 4 + K_TAGS * 4 + 16)
extern __shared__ unsigned char vit_smem[];
__global__ void viterbi_kernel(const float* __restrict__ trans,
                               float* __restrict__ out) {
    unsigned char* bptr = vit_smem;                          // [T][48] u8 = 96KB
    float* fv = (float*)(vit_smem + T_LEN * K_TAGS);         // [2][48]
    float* ps = fv + 2 * K_TAGS;                             // [48] hi-partial score
    int*   pa = (int*)(ps + K_TAGS);                         // [48] hi-partial arg
    int tid = threadIdx.x;  // 96
    int tag = (tid < K_TAGS) ? tid : (tid - K_TAGS);
    int jlo = (tid < K_TAGS) ? 0 : 24;                       // prev range start

    float tr[24];
#pragma unroll
    for (int j = 0; j < 24; j++) tr[j] = trans[tag * K_TAGS + jlo + j];
    if (tid < K_TAGS) fv[tid] = (tid == START_TAG) ? 0.f : -10000.f;
    float featp = g_feats[tag];
    __syncthreads();

    for (int t = 0; t < T_LEN; t++) {
        int cur = (t & 1) * K_TAGS;
        int nxt = K_TAGS - cur;

        float b0 = -3.4e38f, b1 = -3.4e38f, b2 = -3.4e38f, b3 = -3.4e38f;
        int a0 = 0, a1 = 1, a2 = 2, a3 = 3;
#pragma unroll
        for (int j = 0; j < 24; j += 4) {
            float s0 = fv[cur + jlo + j]     + tr[j];
            float s1 = fv[cur + jlo + j + 1] + tr[j + 1];
            float s2 = fv[cur + jlo + j + 2] + tr[j + 2];
            float s3 = fv[cur + jlo + j + 3] + tr[j + 3];
            if (s0 > b0) { b0 = s0; a0 = j; }
            if (s1 > b1) { b1 = s1; a1 = j + 1; }
            if (s2 > b2) { b2 = s2; a2 = j + 2; }
            if (s3 > b3) { b3 = s3; a3 = j + 3; }
        }
        float bv = b0; int ba = a0;
        if (b1 > bv || (b1 == bv && a1 < ba)) { bv = b1; ba = a1; }
        if (b2 > bv || (b2 == bv && a2 < ba)) { bv = b2; ba = a2; }
        if (b3 > bv || (b3 == bv && a3 < ba)) { bv = b3; ba = a3; }
        ba += jlo;

        if (tid >= K_TAGS) {           // upper half publishes its partial
            ps[tag] = bv;
            pa[tag] = ba;
        }
        __syncthreads();

        if (tid < K_TAGS) {
            float hv = ps[tag];
            // strict > : ties go to the low half (smaller indices) = jnp.argmax
            if (hv > bv) { bv = hv; ba = pa[tag]; }
            float feat = featp;
            if (t + 1 < T_LEN) featp = g_feats[(t + 1) * K_TAGS + tag];
            fv[nxt + tag] = bv + feat;
            bptr[t * K_TAGS + tag] = (unsigned char)ba;
        } else {
            if (t + 1 < T_LEN) featp = g_feats[(t + 1) * K_TAGS + tag];
        }
        __syncthreads();
    }

    if (tid == 0) {
        int cur = (T_LEN & 1) * K_TAGS;   // = 0 for even T
        float best = -3.4e38f;
        int btag = 0;
#pragma unroll
        for (int j = 0; j < K_TAGS; j++) {
            float s = fv[cur + j] + trans[STOP_TAG * K_TAGS + j];
            if (s > best) { best = s; btag = j; }
        }
        out[0] = best;
        for (int t = T_LEN - 1; t >= 0; t--) {
            out[1 + t] = (float)btag;
            btag = bptr[t * K_TAGS + btag];
        }
    }
}

// ---------------- launch ----------------
extern "C" void kernel_launch(void* const* d_in, const int* in_sizes, int n_in,
                              void* d_out, int out_size) {
    const int*   sent   = (const int*)d_in[0];
    const float* E      = (const float*)d_in[1];
    const float* W_ih_f = (const float*)d_in[2];
    const float* W_hh_f = (const float*)d_in[3];
    const float* b_ih_f = (const float*)d_in[4];
    const float* b_hh_f = (const float*)d_in[5];
    const float* W_ih_b = (const float*)d_in[6];
    const float* W_hh_b = (const float*)d_in[7];
    const float* b_ih_b = (const float*)d_in[8];
    const float* b_hh_b = (const float*)d_in[9];
    const float* W_out  = (const float*)d_in[10];
    const float* b_out  = (const float*)d_in[11];
    const float* trans  = (const float*)d_in[12];
    float* out = (float*)d_out;

    cudaFuncSetAttribute(viterbi_kernel,
                         cudaFuncAttributeMaxDynamicSharedMemorySize, VIT_SMEM);

    gather_kernel<<<256, 256>>>(sent, E);

    dim3 ggrid(T_LEN / BM, G4 / BN, 2);
    xg_gemm_kernel<<<ggrid, 256>>>(W_ih_f, W_ih_b, b_ih_f, b_hh_f, b_ih_b, b_hh_b);

    lstm_kernel8<<<dim3(8, 2, 1), 512>>>(W_hh_f, W_hh_b);

    feats_gemm_kernel<<<T_LEN / FT_TT, 256>>>(W_out, b_out);

    viterbi_kernel<<<1, 96, VIT_SMEM>>>(trans, out);
}

// round 10
// speedup vs baseline: 1.5302x; 1.0053x over previous
#include <cuda_runtime.h>
#include <cstdint>
#include <math.h>

#define T_LEN  2048
#define D_EMB  300
#define H_DIM  256
#define G4     1024
#define K_TAGS 48
#define START_TAG 46
#define STOP_TAG  47

// ---------------- scratch (device globals; no allocation) ----------------
__device__ float g_x[T_LEN * D_EMB];        // gathered embeddings [T, D]
__device__ float g_xg[2][T_LEN * G4];       // input projections per dir [T, 4H]
__device__ float g_hs[2][T_LEN * H_DIM];    // hidden states per dir, time-aligned
__device__ float g_feats[T_LEN * K_TAGS];   // emission features [T, K]

// ---------------- f32x2 helpers ----------------
__device__ __forceinline__ unsigned long long pack2(float lo, float hi) {
    unsigned long long r;
    asm("mov.b64 %0, {%1,%2};" : "=l"(r) : "f"(lo), "f"(hi));
    return r;
}
__device__ __forceinline__ void unpack2(unsigned long long v, float& lo, float& hi) {
    asm("mov.b64 {%0,%1}, %2;" : "=f"(lo), "=f"(hi) : "l"(v));
}
__device__ __forceinline__ unsigned long long mul2(unsigned long long a, unsigned long long b) {
    unsigned long long d;
    asm("mul.rn.f32x2 %0, %1, %2;" : "=l"(d) : "l"(a), "l"(b));
    return d;
}
__device__ __forceinline__ unsigned long long fma2(unsigned long long a, unsigned long long b,
                                                   unsigned long long c) {
    unsigned long long d;
    asm("fma.rn.f32x2 %0, %1, %2, %3;" : "=l"(d) : "l"(a), "l"(b), "l"(c));
    return d;
}

// ---------------- 1) embedding gather ----------------
__global__ void gather_kernel(const int* __restrict__ sent,
                              const float* __restrict__ E) {
    int idx = blockIdx.x * blockDim.x + threadIdx.x;
    int total = T_LEN * D_EMB;
    for (; idx < total; idx += gridDim.x * blockDim.x) {
        int t = idx / D_EMB;
        int d = idx - t * D_EMB;
        long long row = sent[t];
        g_x[idx] = E[row * D_EMB + d];
    }
}

// ---------------- 2) xg GEMM: [T,D] @ [4H,D]^T + (b_ih + b_hh) ----------------
#define BM 64
#define BN 64
#define BK 12
__global__ void xg_gemm_kernel(const float* __restrict__ Wf,
                               const float* __restrict__ Wb,
                               const float* __restrict__ bihf,
                               const float* __restrict__ bhhf,
                               const float* __restrict__ bihb,
                               const float* __restrict__ bhhb) {
    int dir = blockIdx.z;
    const float* W  = dir ? Wb   : Wf;
    const float* b1 = dir ? bihb : bihf;
    const float* b2 = dir ? bhhb : bhhf;

    __shared__ float As[BK][BM];
    __shared__ float Bs[BK][BN];

    int t0 = blockIdx.x * BM;
    int r0 = blockIdx.y * BN;
    int tid = threadIdx.x;           // 256 threads
    int tx = tid & 15;
    int ty = tid >> 4;

    float acc[4][4];
#pragma unroll
    for (int i = 0; i < 4; i++)
#pragma unroll
        for (int j = 0; j < 4; j++) acc[i][j] = 0.f;

    for (int k0 = 0; k0 < D_EMB; k0 += BK) {   // 300 = 25 * 12, no guards
#pragma unroll
        for (int l2 = 0; l2 < 3; l2++) {
            int idx = tid + l2 * 256;       // 0..767
            int row = idx / 12;             // 0..63
            int kk  = idx - row * 12;
            int tg = t0 + row;
            int ts = dir ? (T_LEN - 1 - tg) : tg;
            As[kk][row] = g_x[ts * D_EMB + k0 + kk];
            Bs[kk][row] = W[(r0 + row) * D_EMB + k0 + kk];
        }
        __syncthreads();
#pragma unroll
        for (int kk = 0; kk < BK; kk++) {
            float ra[4], rb[4];
#pragma unroll
            for (int i = 0; i < 4; i++) ra[i] = As[kk][ty * 4 + i];
#pragma unroll
            for (int j = 0; j < 4; j++) rb[j] = Bs[kk][tx * 4 + j];
#pragma unroll
            for (int i = 0; i < 4; i++)
#pragma unroll
                for (int j = 0; j < 4; j++) acc[i][j] += ra[i] * rb[j];
        }
        __syncthreads();
    }

#pragma unroll
    for (int i = 0; i < 4; i++) {
        int t = t0 + ty * 4 + i;
#pragma unroll
        for (int j = 0; j < 4; j++) {
            int r = r0 + tx * 4 + j;
            g_xg[dir][t * G4 + r] = acc[i][j] + b1[r] + b2[r];
        }
    }
}

// ---------------- 3) LSTM recurrence: 8-CTA cluster per direction ----------------
// Frozen champion sync protocol (split barrier.cluster per step). Compute:
// rows land on lane bits <4,3,2> after 3 scatter rounds, partials combine
// over bits <1,0> (5 dependent shfl rounds total). Gate gather at lanes
// 16du+4g; h pair exchange via one shfl_xor(16). Lanes 0-7 fan the packed h
// pair to all 8 CTAs in one warp store instruction. The next-step xg LDG is
// issued INSIDE the barrier window (after arrive, before wait) so its latency
// hides under the barrier release.
__global__ void __launch_bounds__(512, 1) __cluster_dims__(8, 1, 1)
lstm_kernel8(const float* __restrict__ Whf, const float* __restrict__ Whb) {
    __shared__ float h_buf[2][H_DIM];

    int dir = blockIdx.y;
    const float* Whh = dir ? Whb : Whf;
    const float* xg = g_xg[dir];
    float* hs = g_hs[dir];

    uint32_t rank;
    asm("mov.u32 %0, %%cluster_ctarank;" : "=r"(rank));

    int tid = threadIdx.x;
    int w = tid >> 5;
    int l = tid & 31;
    int r = (l >> 2) & 7;          // W row this lane finalizes (lane bits 4,3,2)
    int gate = r & 3;
    int du = r >> 2;               // which of the warp's 2 units (== l>>4)
    int xg_col = gate * H_DIM + (int)rank * 32 + 2 * w + du;

    // weight rows q: gate = q&3, unit-offset = q>>2; lane covers k [8l,8l+8)
    unsigned long long w2[8][4];
#pragma unroll
    for (int q = 0; q < 8; q++) {
        int row = (q & 3) * H_DIM + (int)rank * 32 + 2 * w + (q >> 2);
        const float4* p = (const float4*)(Whh + (size_t)row * H_DIM + l * 8);
        float4 a = p[0];
        float4 b = p[1];
        w2[q][0] = pack2(a.x, a.y); w2[q][1] = pack2(a.z, a.w);
        w2[q][2] = pack2(b.x, b.y); w2[q][3] = pack2(b.z, b.w);
    }

    if (tid < 2 * H_DIM) ((float*)h_buf)[tid] = 0.f;
    uint32_t hb = (uint32_t)__cvta_generic_to_shared(&h_buf[0][0]);

    uint32_t rH[8];
#pragma unroll
    for (int tg = 0; tg < 8; tg++) {
        asm("mapa.shared::cluster.u32 %0, %1, %2;" : "=r"(rH[tg]) : "r"(hb), "r"(tg));
    }

    __syncthreads();
    asm volatile("barrier.cluster.arrive.aligned;" ::: "memory");
    asm volatile("barrier.cluster.wait.aligned;" ::: "memory");

    float c_reg = 0.f;
    float xg_pref = xg[xg_col];    // xg for t=0
    const float LOG2E = 1.4426950408889634f;
    const float act_a = (gate == 2) ? (2.f * LOG2E) : (-LOG2E);
    const bool  is_tanh = (gate == 2);

#pragma unroll 1
    for (int t = 0; t < T_LEN; t++) {
        int cur = t & 1;
        int nxt = cur ^ 1;

        float4 ha = *(const float4*)&h_buf[cur][l * 8];
        float4 hc = *(const float4*)&h_buf[cur][l * 8 + 4];
        unsigned long long h2[4] = { pack2(ha.x, ha.y), pack2(ha.z, ha.w),
                                     pack2(hc.x, hc.y), pack2(hc.z, hc.w) };
        float v[8];
#pragma unroll
        for (int q = 0; q < 8; q++) {
            unsigned long long acc = mul2(w2[q][0], h2[0]);
            acc = fma2(w2[q][1], h2[1], acc);
            acc = fma2(w2[q][2], h2[2], acc);
            acc = fma2(w2[q][3], h2[3], acc);
            float lo, hi;
            unpack2(acc, lo, hi);
            v[q] = lo + hi;
        }

        // reduce-scatter onto lane bits 4,3,2 (row = (l>>2)&7)
#pragma unroll
        for (int i = 0; i < 4; i++) {
            float send = (l & 16) ? v[i] : v[i + 4];
            float recv = __shfl_xor_sync(0xffffffffu, send, 16);
            float keep = (l & 16) ? v[i + 4] : v[i];
            v[i] = keep + recv;
        }
#pragma unroll
        for (int i = 0; i < 2; i++) {
            float send = (l & 8) ? v[i] : v[i + 2];
            float recv = __shfl_xor_sync(0xffffffffu, send, 8);
            float keep = (l & 8) ? v[i + 2] : v[i];
            v[i] = keep + recv;
        }
        {
            float send = (l & 4) ? v[0] : v[1];
            float recv = __shfl_xor_sync(0xffffffffu, send, 4);
            float keep = (l & 4) ? v[1] : v[0];
            v[0] = keep + recv;
        }
        // combine the 4 partials living at lane bits 1,0
        float x = v[0];
        x += __shfl_xor_sync(0xffffffffu, x, 1);
        x += __shfl_xor_sync(0xffffffffu, x, 2);

        float pre = x + xg_pref;

        // branch-free activation: gate 2 -> tanh, else sigmoid (EX2 + RCP)
        float e = exp2f(act_a * pre);
        float z = __fdividef(1.f, 1.f + e);
        float act = is_tanh ? fmaf(-2.f, z, 1.f) : z;

        // gather i,f,g,o for this lane's unit du: rows du*4+g at lanes 16du+4g
        int gbase = du << 4;
        float iv = __shfl_sync(0xffffffffu, act, gbase);
        float fv = __shfl_sync(0xffffffffu, act, gbase + 4);
        float gg = __shfl_sync(0xffffffffu, act, gbase + 8);
        float ov = __shfl_sync(0xffffffffu, act, gbase + 12);

        c_reg = fmaf(fv, c_reg, iv * gg);
        float e2 = exp2f(2.f * LOG2E * c_reg);
        float hval = ov * fmaf(-2.f, __fdividef(1.f, 1.f + e2), 1.f);
        // hval identical within each du half (lanes 0-15: unit 2w; 16-31: 2w+1)

        // single xor-16: every lane obtains the other unit's h
        float h_other = __shfl_xor_sync(0xffffffffu, hval, 16);

        uint32_t off = (uint32_t)((nxt * H_DIM + (int)rank * 32 + 2 * w) * 4);
        if (l < 8) {   // lanes 0-7: du=0 -> hval=h0, h_other=h1
            unsigned long long pk = pack2(hval, h_other);
            asm volatile("st.shared::cluster.b64 [%0], %1;"
                         :: "r"(rH[l] + off), "l"(pk) : "memory");
        }

        asm volatile("barrier.cluster.arrive.aligned;" ::: "memory");

        // issue next-step xg load inside the barrier window (latency hidden)
        if (t + 1 < T_LEN)
            xg_pref = xg[(size_t)(t + 1) * G4 + xg_col];

        if (l == 8) {  // du=0: hval=h0, h_other=h1
            int tout = dir ? (T_LEN - 1 - t) : t;
            *(float2*)&hs[(size_t)tout * H_DIM + rank * 32 + 2 * w] =
                make_float2(hval, h_other);
        }

        asm volatile("barrier.cluster.wait.aligned;" ::: "memory");
    }

    asm volatile("barrier.cluster.arrive.aligned;" ::: "memory");
    asm volatile("barrier.cluster.wait.aligned;" ::: "memory");
}

// ---------------- 4) feats GEMM: [T,512] @ [48,512]^T + b_out ----------------
#define FT_TT 64
__global__ void feats_gemm_kernel(const float* __restrict__ W_out,
                                  const float* __restrict__ b_out) {
    __shared__ float As[32][FT_TT];   // [j][t]
    __shared__ float Bs[32][K_TAGS];  // [j][k]

    int t0 = blockIdx.x * FT_TT;
    int tid = threadIdx.x;            // 256
    int tx = tid & 15;                // k-group: 3 tags
    int ty = tid >> 4;                // t-group: 4 steps

    float acc[4][3];
#pragma unroll
    for (int i = 0; i < 4; i++)
#pragma unroll
        for (int k = 0; k < 3; k++) acc[i][k] = 0.f;

    for (int j0 = 0; j0 < 2 * H_DIM; j0 += 32) {
#pragma unroll
        for (int i = 0; i < 8; i++) {
            int idx = tid + i * 256;        // 0..2047
            int jj = idx & 31;
            int tt = idx >> 5;
            int j = j0 + jj;
            float hv = (j < H_DIM)
                ? g_hs[0][(size_t)(t0 + tt) * H_DIM + j]
                : g_hs[1][(size_t)(t0 + tt) * H_DIM + (j - H_DIM)];
            As[jj][tt] = hv;
        }
        // coalesced W_out load: consecutive threads read consecutive j
#pragma unroll
        for (int i = 0; i < 6; i++) {
            int idx = tid + i * 256;        // 0..1535 = 32 j x 48 k
            int jj = idx & 31;
            int k = idx >> 5;               // 0..47
            Bs[jj][k] = W_out[(size_t)k * (2 * H_DIM) + j0 + jj];
        }
        __syncthreads();
#pragma unroll
        for (int jj = 0; jj < 32; jj++) {
            float a[4], b[3];
#pragma unroll
            for (int i = 0; i < 4; i++) a[i] = As[jj][ty * 4 + i];
#pragma unroll
            for (int k = 0; k < 3; k++) b[k] = Bs[jj][tx * 3 + k];
#pragma unroll
            for (int i = 0; i < 4; i++)
#pragma unroll
                for (int k = 0; k < 3; k++) acc[i][k] += a[i] * b[k];
        }
        __syncthreads();
    }

#pragma unroll
    for (int i = 0; i < 4; i++) {
        int t = t0 + ty * 4 + i;
#pragma unroll
        for (int k = 0; k < 3; k++) {
            int kk = tx * 3 + k;
            g_feats[t * K_TAGS + kk] = acc[i][k] + b_out[kk];
        }
    }
}

// ---------------- 5) Viterbi + backtrace (single CTA, 96 threads, 1 sync/step) ----------------
// Warp w, lane l: tag = w*16 + (l&15), half = l>>4 owns prev range
// [half*24, half*24+24). The two halves of a tag live in the SAME warp and
// combine via shfl_xor(16) with first-index tie-breaking (half0 owns smaller
// prev indices; half1 wins only on strict >). One __syncthreads per step.
#define VIT_SMEM (T_LEN * K_TAGS + 2 * K_TAGS * 4 + 16)
extern __shared__ unsigned char vit_smem[];
__global__ void viterbi_kernel(const float* __restrict__ trans,
                               float* __restrict__ out) {
    unsigned char* bptr = vit_smem;                          // [T][48] u8 = 96KB
    float* fv = (float*)(vit_smem + T_LEN * K_TAGS);         // [2][48]
    int tid = threadIdx.x;  // 96
    int l = tid & 31;
    int wid = tid >> 5;                    // 0..2
    int tag = wid * 16 + (l & 15);
    int half = l >> 4;                     // 0 or 1
    int jlo = half * 24;

    float tr[24];
#pragma unroll
    for (int j = 0; j < 24; j++) tr[j] = trans[tag * K_TAGS + jlo + j];
    if (half == 0) fv[tag] = (tag == START_TAG) ? 0.f : -10000.f;
    float featp = (half == 0) ? g_feats[tag] : 0.f;
    __syncthreads();

    for (int t = 0; t < T_LEN; t++) {
        int cur = (t & 1) * K_TAGS;
        int nxt = K_TAGS - cur;

        // 4 independent max chains over this half's 24 prev-tags
        float b0 = -3.4e38f, b1 = -3.4e38f, b2 = -3.4e38f, b3 = -3.4e38f;
        int a0 = 0, a1 = 1, a2 = 2, a3 = 3;
#pragma unroll
        for (int j = 0; j < 24; j += 4) {
            float s0 = fv[cur + jlo + j]     + tr[j];
            float s1 = fv[cur + jlo + j + 1] + tr[j + 1];
            float s2 = fv[cur + jlo + j + 2] + tr[j + 2];
            float s3 = fv[cur + jlo + j + 3] + tr[j + 3];
            if (s0 > b0) { b0 = s0; a0 = j; }
            if (s1 > b1) { b1 = s1; a1 = j + 1; }
            if (s2 > b2) { b2 = s2; a2 = j + 2; }
            if (s3 > b3) { b3 = s3; a3 = j + 3; }
        }
        float bv = b0; int ba = a0;
        if (b1 > bv || (b1 == bv && a1 < ba)) { bv = b1; ba = a1; }
        if (b2 > bv || (b2 == bv && a2 < ba)) { bv = b2; ba = a2; }
        if (b3 > bv || (b3 == bv && a3 < ba)) { bv = b3; ba = a3; }
        ba += jlo;

        // cross-half combine inside the warp (half0 <-> half1 at xor 16)
        float ov = __shfl_xor_sync(0xffffffffu, bv, 16);
        int   oa = __shfl_xor_sync(0xffffffffu, ba, 16);
        if (half == 0) {
            // strict > : ties keep half0 (smaller prev indices) = jnp.argmax
            if (ov > bv) { bv = ov; ba = oa; }
            fv[nxt + tag] = bv + featp;
            bptr[t * K_TAGS + tag] = (unsigned char)ba;
            if (t + 1 < T_LEN) featp = g_feats[(t + 1) * K_TAGS + tag];
        }
        __syncthreads();
    }

    if (tid == 0) {
        int cur = (T_LEN & 1) * K_TAGS;   // = 0 for even T
        float best = -3.4e38f;
        int btag = 0;
#pragma unroll
        for (int j = 0; j < K_TAGS; j++) {
            float s = fv[cur + j] + trans[STOP_TAG * K_TAGS + j];
            if (s > best) { best = s; btag = j; }
        }
        out[0] = best;
        for (int t = T_LEN - 1; t >= 0; t--) {
            out[1 + t] = (float)btag;
            btag = bptr[t * K_TAGS + btag];
        }
    }
}

// ---------------- launch ----------------
extern "C" void kernel_launch(void* const* d_in, const int* in_sizes, int n_in,
                              void* d_out, int out_size) {
    const int*   sent   = (const int*)d_in[0];
    const float* E      = (const float*)d_in[1];
    const float* W_ih_f = (const float*)d_in[2];
    const float* W_hh_f = (const float*)d_in[3];
    const float* b_ih_f = (const float*)d_in[4];
    const float* b_hh_f = (const float*)d_in[5];
    const float* W_ih_b = (const float*)d_in[6];
    const float* W_hh_b = (const float*)d_in[7];
    const float* b_ih_b = (const float*)d_in[8];
    const float* b_hh_b = (const float*)d_in[9];
    const float* W_out  = (const float*)d_in[10];
    const float* b_out  = (const float*)d_in[11];
    const float* trans  = (const float*)d_in[12];
    float* out = (float*)d_out;

    cudaFuncSetAttribute(viterbi_kernel,
                         cudaFuncAttributeMaxDynamicSharedMemorySize, VIT_SMEM);

    gather_kernel<<<256, 256>>>(sent, E);

    dim3 ggrid(T_LEN / BM, G4 / BN, 2);
    xg_gemm_kernel<<<ggrid, 256>>>(W_ih_f, W_ih_b, b_ih_f, b_hh_f, b_ih_b, b_hh_b);

    lstm_kernel8<<<dim3(8, 2, 1), 512>>>(W_hh_f, W_hh_b);

    feats_gemm_kernel<<<T_LEN / FT_TT, 256>>>(W_out, b_out);

    viterbi_kernel<<<1, 96, VIT_SMEM>>>(trans, out);
}